// round 14
// baseline (speedup 1.0000x reference)
#include <cuda_runtime.h>
#include <cuda_bf16.h>
#include <cstdint>

#define MDIM  128
#define FEAT  8256
#define HID   1651
#define NP    1664          // 13*128
#define KP    8320          // 130*64
#define BATCH 4096
#define ROWB  (KP * 2)
#define KSTG  130

#define STG_A       16384
#define STG_BYTES   32768
#define NSTG        3
#define SMEM_TOTAL  (NSTG * STG_BYTES)     // 96 KB per CTA, 2 CTAs/SM

#define NT 13
#define NTILES 416
#define FULLW  296          // full-tile work items
#define TOTW   536          // 296 full + 240 half
#define GRID   296

// ---------------- device scratch ----------------
__device__ __nv_bfloat16 g_xb [(size_t)BATCH * KP];
__device__ __nv_bfloat16 g_w1b[(size_t)NP    * KP];
__device__ float g_b1[NP];
__device__ float g_w2[NP];
__device__ float g_logits[BATCH];
__device__ int   g_counter;

// ---------------- helpers ----------------
__device__ __forceinline__ uint32_t smem_u32(const void* p) {
    uint32_t a;
    asm("{ .reg .u64 t; cvta.to.shared.u64 t, %1; cvt.u32.u64 %0, t; }" : "=r"(a) : "l"(p));
    return a;
}
#define SWZ128(off) ((off) ^ (((off) >> 3) & 0x70))

__device__ __forceinline__ void ldsm_x4(uint32_t& r0, uint32_t& r1, uint32_t& r2, uint32_t& r3,
                                        uint32_t addr) {
    asm volatile("ldmatrix.sync.aligned.m8n8.x4.shared.b16 {%0,%1,%2,%3}, [%4];"
                 : "=r"(r0), "=r"(r1), "=r"(r2), "=r"(r3) : "r"(addr));
}
__device__ __forceinline__ void mma_bf16(float* c, const uint32_t* a, const uint32_t* b) {
    asm volatile(
        "mma.sync.aligned.m16n8k16.row.col.f32.bf16.bf16.f32 "
        "{%0,%1,%2,%3}, {%4,%5,%6,%7}, {%8,%9}, {%0,%1,%2,%3};"
        : "+f"(c[0]), "+f"(c[1]), "+f"(c[2]), "+f"(c[3])
        : "r"(a[0]), "r"(a[1]), "r"(a[2]), "r"(a[3]), "r"(b[0]), "r"(b[1]));
}

// ---------------- prep kernels ----------------
__global__ void prep_small(const float* __restrict__ b1, const float* __restrict__ w2) {
    int i = blockIdx.x * blockDim.x + threadIdx.x;
    if (i == 0) g_counter = 0;
    if (i < NP) {
        g_b1[i] = (i < HID) ? b1[i] : 0.0f;
        g_w2[i] = (i < HID) ? w2[i] : 0.0f;
    }
    if (i < BATCH) g_logits[i] = 0.0f;
}

__global__ void prep_w1b(const float* __restrict__ W1) {
    int n  = blockIdx.y;
    int k4 = blockIdx.x * blockDim.x + threadIdx.x;
    if (k4 >= KP / 4) return;
    __nv_bfloat16 o[4] = {__float2bfloat16(0.f), __float2bfloat16(0.f),
                          __float2bfloat16(0.f), __float2bfloat16(0.f)};
    if (n < HID) {
        int k = k4 * 4;
        if (k + 3 < FEAT) {
            float4 v = *(const float4*)&W1[(size_t)n * FEAT + k];
            o[0] = __float2bfloat16(v.x); o[1] = __float2bfloat16(v.y);
            o[2] = __float2bfloat16(v.z); o[3] = __float2bfloat16(v.w);
        } else {
#pragma unroll
            for (int j = 0; j < 4; j++)
                if (k + j < FEAT) o[j] = __float2bfloat16(W1[(size_t)n * FEAT + k + j]);
        }
    }
    *(uint2*)&g_w1b[(size_t)n * KP + k4 * 4] = *(uint2*)o;
}

__global__ __launch_bounds__(256) void triub(const float* __restrict__ sim) {
    int b   = blockIdx.x;
    int tid = threadIdx.x;
    const float* base = sim + (size_t)b * MDIM * MDIM;
    __nv_bfloat16* out = g_xb + (size_t)b * KP;
#pragma unroll
    for (int it = 0; it < 16; ++it) {
        int idx = tid + it * 256;
        int i = idx >> 5;
        int g = idx & 31;
        int j0 = g * 4;
        if (j0 + 3 >= i) {
            float4 v = *(const float4*)&base[i * MDIM + j0];
            int rowoff = i * MDIM - (i * (i - 1)) / 2 - i;
            float vv[4] = {v.x, v.y, v.z, v.w};
#pragma unroll
            for (int l = 0; l < 4; l++) {
                int j = j0 + l;
                if (j >= i) out[rowoff + j] = __float2bfloat16(vv[l]);
            }
        }
    }
    if (tid < KP - FEAT) out[FEAT + tid] = __float2bfloat16(0.f);
}

// ---------------- tile worker: NI = n8-frags per warp (8: N=128 tile, 4: N=64) ----------------
template<int NI>
__device__ __forceinline__ void do_tile(uint32_t sbase, int m0, int n0,
                                        int tid, int wid, int lid) {
    const int wm = wid & 3;
    const int wn = wid >> 2;

    // consumer offsets (row-invariant swizzle XOR)
    const int aRow0 = wm * 32 + ((lid >> 3) & 1) * 8 + (lid & 7);
    const int aCol  = (lid >> 4) * 16;
    const uint32_t aXor = (uint32_t)((aRow0 & 7) << 4);
    const int bRow0 = wn * (NI * 8) + (lid >> 4) * 8 + (lid & 7);
    const int bCol  = ((lid >> 3) & 1) * 16;
    const uint32_t bXor = (uint32_t)((bRow0 & 7) << 4);

    uint32_t aOff[4], bOff[4];
#pragma unroll
    for (int ks = 0; ks < 4; ks++) {
        aOff[ks] = (uint32_t)(aRow0 * 128) + (((uint32_t)(aCol + ks * 32)) ^ aXor);
        bOff[ks] = STG_A + (uint32_t)(bRow0 * 128) + (((uint32_t)(bCol + ks * 32)) ^ bXor);
    }

    // producer
    const int pr = tid >> 3;
    const int pc = tid & 7;
    const uint32_t dstSw = SWZ128((uint32_t)(pr * 128 + pc * 16));
    const uint8_t* aSrc = (const uint8_t*)g_xb  + (size_t)(m0 + pr) * ROWB + pc * 16;
    const uint8_t* bSrc = (const uint8_t*)g_w1b + (size_t)(n0 + pr) * ROWB + pc * 16;

    float acc[2][NI][4];
#pragma unroll
    for (int mi = 0; mi < 2; mi++)
#pragma unroll
        for (int ni = 0; ni < NI; ni++)
#pragma unroll
            for (int c = 0; c < 4; c++) acc[mi][ni][c] = 0.0f;

    auto load_stage = [&](uint32_t stgOff) {
        uint32_t d = sbase + stgOff + dstSw;
#pragma unroll
        for (int it = 0; it < 4; ++it)
            asm volatile("cp.async.cg.shared.global [%0], [%1], 16;"
                         :: "r"(d + it * 4096), "l"(aSrc + (size_t)it * 32 * ROWB) : "memory");
#pragma unroll
        for (int it = 0; it < NI / 2; ++it)
            asm volatile("cp.async.cg.shared.global [%0], [%1], 16;"
                         :: "r"(d + STG_A + it * 4096), "l"(bSrc + (size_t)it * 32 * ROWB) : "memory");
        asm volatile("cp.async.commit_group;" ::: "memory");
        aSrc += 128; bSrc += 128;
    };

    load_stage(0);
    load_stage(STG_BYTES);
    uint32_t cOff = 0, lOff = 2 * STG_BYTES;

    for (int s = 0; s < KSTG; ++s) {
        asm volatile("cp.async.wait_group 1;" ::: "memory");
        __syncthreads();

        if (s + 2 < KSTG) {
            load_stage(lOff);
            lOff = (lOff == 2 * STG_BYTES) ? 0u : lOff + STG_BYTES;
        } else {
            asm volatile("cp.async.commit_group;" ::: "memory");
        }

        const uint32_t stg = sbase + cOff;
        cOff = (cOff == 2 * STG_BYTES) ? 0u : cOff + STG_BYTES;

#pragma unroll
        for (int ksi = 0; ksi < 4; ++ksi) {
            const int ks = (ksi + wid) & 3;     // stagger warps' LDSM bursts
            const uint32_t bb = stg + bOff[ks];
            uint32_t b[NI][2];
#pragma unroll
            for (int pp = 0; pp < NI / 2; pp++) {
                uint32_t r0, r1, r2, r3;
                ldsm_x4(r0, r1, r2, r3, bb + pp * 2048);
                b[2 * pp][0] = r0; b[2 * pp][1] = r1;
                b[2 * pp + 1][0] = r2; b[2 * pp + 1][1] = r3;
            }
            const uint32_t aa = stg + aOff[ks];
            uint32_t a[2][4];
            ldsm_x4(a[0][0], a[0][1], a[0][2], a[0][3], aa);
            ldsm_x4(a[1][0], a[1][1], a[1][2], a[1][3], aa + 2048);
#pragma unroll
            for (int mi = 0; mi < 2; mi++)
#pragma unroll
                for (int ni = 0; ni < NI; ni++)
                    mma_bf16(acc[mi][ni], a[mi], b[ni]);
        }
    }
    __syncthreads();   // all LDSM done before buffers are reused

    // fused epilogue
    const int qrow = lid >> 2;
    const int qcol = lid & 3;
#pragma unroll
    for (int mi = 0; mi < 2; mi++) {
        float r0 = 0.f, r1 = 0.f;
#pragma unroll
        for (int ni = 0; ni < NI; ni++) {
            int n = n0 + wn * (NI * 8) + ni * 8 + qcol * 2;
            float b1a = g_b1[n],     w2a = g_w2[n];
            float b1b = g_b1[n + 1], w2b = g_w2[n + 1];
            r0 += fmaxf(acc[mi][ni][0] + b1a, 0.f) * w2a
                + fmaxf(acc[mi][ni][1] + b1b, 0.f) * w2b;
            r1 += fmaxf(acc[mi][ni][2] + b1a, 0.f) * w2a
                + fmaxf(acc[mi][ni][3] + b1b, 0.f) * w2b;
        }
        r0 += __shfl_xor_sync(0xffffffffu, r0, 1);
        r0 += __shfl_xor_sync(0xffffffffu, r0, 2);
        r1 += __shfl_xor_sync(0xffffffffu, r1, 1);
        r1 += __shfl_xor_sync(0xffffffffu, r1, 2);
        if (qcol == 0) {
            int row = m0 + wm * 32 + mi * 16 + qrow;
            atomicAdd(&g_logits[row],     r0);
            atomicAdd(&g_logits[row + 8], r1);
        }
    }
}

// ---- bf16 GEMM: 2 CTAs/SM, dynamic mixed-granularity work queue ----
__global__ __launch_bounds__(256, 2) void gemm_bf16() {
    extern __shared__ __align__(1024) uint8_t smem[];
    __shared__ int s_w;
    const uint32_t sbase = smem_u32(smem);
    const int tid = threadIdx.x;
    const int wid = tid >> 5;
    const int lid = tid & 31;

    for (;;) {
        if (tid == 0) s_w = atomicAdd(&g_counter, 1);
        __syncthreads();
        const int w = s_w;
        __syncthreads();
        if (w >= TOTW) break;

        if (w < FULLW) {
            const int t  = w;
            do_tile<8>(sbase, (t / NT) * 128, (t % NT) * 128, tid, wid, lid);
        } else {
            const int h  = w - FULLW;
            const int t  = FULLW + (h >> 1);
            const int m0 = (t / NT) * 128;
            const int n0 = (t % NT) * 128 + (h & 1) * 64;
            do_tile<4>(sbase, m0, n0, tid, wid, lid);
        }
    }
}

// ---------------- finalize ----------------
__global__ void finalize(const float* __restrict__ b2, float* __restrict__ out) {
    int i = blockIdx.x * blockDim.x + threadIdx.x;
    if (i < BATCH) {
        float z = g_logits[i] + b2[0];
        out[i] = 1.0f / (1.0f + expf(-z));
    }
}

// ---------------- launch ----------------
extern "C" void kernel_launch(void* const* d_in, const int* in_sizes, int n_in,
                              void* d_out, int out_size) {
    const float* sim = (const float*)d_in[0];
    const float* W1  = (const float*)d_in[1];
    const float* b1  = (const float*)d_in[2];
    const float* W2  = (const float*)d_in[3];
    const float* b2  = (const float*)d_in[4];
    float* out = (float*)d_out;

    cudaFuncSetAttribute(gemm_bf16, cudaFuncAttributeMaxDynamicSharedMemorySize, SMEM_TOTAL);

    prep_small<<<(BATCH + 255) / 256, 256>>>(b1, W2);
    prep_w1b<<<dim3((KP / 4 + 255) / 256, NP), 256>>>(W1);
    triub<<<BATCH, 256>>>(sim);
    gemm_bf16<<<GRID, 256, SMEM_TOTAL>>>();
    finalize<<<(BATCH + 255) / 256, 256>>>(b2, out);
}

// round 15
// speedup vs baseline: 1.0316x; 1.0316x over previous
#include <cuda_runtime.h>
#include <cuda_bf16.h>
#include <cstdint>

#define MDIM  128
#define FEAT  8256
#define HID   1651
#define NP    1664          // 13*128
#define KP    8320          // 130*64
#define BATCH 4096
#define ROWB  (KP * 2)
#define KSTG  130

#define STG_A       16384
#define STG_BYTES   32768
#define NSTG        3
#define SMEM_TOTAL  (NSTG * STG_BYTES)     // 96 KB per CTA, 2 CTAs/SM

#define NT 13
#define NTILES 416
#define FULL_T 296          // statically scheduled full tiles
#define TAIL_T 120          // tiles split into 2 K-halves each
#define TAIL_ITEMS 240
#define GRID   296

// ---------------- device scratch ----------------
__device__ __nv_bfloat16 g_xb [(size_t)BATCH * KP];
__device__ __nv_bfloat16 g_w1b[(size_t)NP    * KP];
__device__ float g_b1[NP];
__device__ float g_w2[NP];
__device__ float g_logits[BATCH];
__device__ int   g_counter;
__device__ float g_h[2][TAIL_T][128 * 128];   // pre-relu K-half partials (15.7 MB)

// ---------------- helpers ----------------
__device__ __forceinline__ uint32_t smem_u32(const void* p) {
    uint32_t a;
    asm("{ .reg .u64 t; cvta.to.shared.u64 t, %1; cvt.u32.u64 %0, t; }" : "=r"(a) : "l"(p));
    return a;
}
#define SWZ128(off) ((off) ^ (((off) >> 3) & 0x70))

__device__ __forceinline__ void ldsm_x4(uint32_t& r0, uint32_t& r1, uint32_t& r2, uint32_t& r3,
                                        uint32_t addr) {
    asm volatile("ldmatrix.sync.aligned.m8n8.x4.shared.b16 {%0,%1,%2,%3}, [%4];"
                 : "=r"(r0), "=r"(r1), "=r"(r2), "=r"(r3) : "r"(addr));
}
__device__ __forceinline__ void mma_bf16(float* c, const uint32_t* a, const uint32_t* b) {
    asm volatile(
        "mma.sync.aligned.m16n8k16.row.col.f32.bf16.bf16.f32 "
        "{%0,%1,%2,%3}, {%4,%5,%6,%7}, {%8,%9}, {%0,%1,%2,%3};"
        : "+f"(c[0]), "+f"(c[1]), "+f"(c[2]), "+f"(c[3])
        : "r"(a[0]), "r"(a[1]), "r"(a[2]), "r"(a[3]), "r"(b[0]), "r"(b[1]));
}

// ---------------- prep kernels ----------------
__global__ void prep_small(const float* __restrict__ b1, const float* __restrict__ w2) {
    int i = blockIdx.x * blockDim.x + threadIdx.x;
    if (i == 0) g_counter = 0;
    if (i < NP) {
        g_b1[i] = (i < HID) ? b1[i] : 0.0f;
        g_w2[i] = (i < HID) ? w2[i] : 0.0f;
    }
    if (i < BATCH) g_logits[i] = 0.0f;
}

__global__ void prep_w1b(const float* __restrict__ W1) {
    int n  = blockIdx.y;
    int k4 = blockIdx.x * blockDim.x + threadIdx.x;
    if (k4 >= KP / 4) return;
    __nv_bfloat16 o[4] = {__float2bfloat16(0.f), __float2bfloat16(0.f),
                          __float2bfloat16(0.f), __float2bfloat16(0.f)};
    if (n < HID) {
        int k = k4 * 4;
        if (k + 3 < FEAT) {
            float4 v = *(const float4*)&W1[(size_t)n * FEAT + k];
            o[0] = __float2bfloat16(v.x); o[1] = __float2bfloat16(v.y);
            o[2] = __float2bfloat16(v.z); o[3] = __float2bfloat16(v.w);
        } else {
#pragma unroll
            for (int j = 0; j < 4; j++)
                if (k + j < FEAT) o[j] = __float2bfloat16(W1[(size_t)n * FEAT + k + j]);
        }
    }
    *(uint2*)&g_w1b[(size_t)n * KP + k4 * 4] = *(uint2*)o;
}

__global__ __launch_bounds__(256) void triub(const float* __restrict__ sim) {
    int b   = blockIdx.x;
    int tid = threadIdx.x;
    const float* base = sim + (size_t)b * MDIM * MDIM;
    __nv_bfloat16* out = g_xb + (size_t)b * KP;
#pragma unroll
    for (int it = 0; it < 16; ++it) {
        int idx = tid + it * 256;
        int i = idx >> 5;
        int g = idx & 31;
        int j0 = g * 4;
        if (j0 + 3 >= i) {
            float4 v = *(const float4*)&base[i * MDIM + j0];
            int rowoff = i * MDIM - (i * (i - 1)) / 2 - i;
            float vv[4] = {v.x, v.y, v.z, v.w};
#pragma unroll
            for (int l = 0; l < 4; l++) {
                int j = j0 + l;
                if (j >= i) out[rowoff + j] = __float2bfloat16(vv[l]);
            }
        }
    }
    if (tid < KP - FEAT) out[FEAT + tid] = __float2bfloat16(0.f);
}

// ---------------- tile worker (128x128, 8 warps of 32x64) ----------------
// TAIL=false: full K, fused epilogue to logits. TAIL=true: 65-stage K-half,
// raw accumulators stored to hbuf (pre-relu merge happens in tailfin).
template<bool TAIL>
__device__ __forceinline__ void do_tile(uint32_t sbase, int m0, int n0,
                                        int kstart, float* hbuf,
                                        int tid, int wid, int lid) {
    const int wm = wid & 3;
    const int wn = wid >> 2;
    const int nst = TAIL ? (KSTG / 2) : KSTG;

    // consumer offsets (row-invariant swizzle XOR)
    const int aRow0 = wm * 32 + ((lid >> 3) & 1) * 8 + (lid & 7);
    const int aCol  = (lid >> 4) * 16;
    const uint32_t aXor = (uint32_t)((aRow0 & 7) << 4);
    const int bRow0 = wn * 64 + (lid >> 4) * 8 + (lid & 7);
    const int bCol  = ((lid >> 3) & 1) * 16;
    const uint32_t bXor = (uint32_t)((bRow0 & 7) << 4);

    uint32_t aOff[4], bOff[4];
#pragma unroll
    for (int ks = 0; ks < 4; ks++) {
        aOff[ks] = (uint32_t)(aRow0 * 128) + (((uint32_t)(aCol + ks * 32)) ^ aXor);
        bOff[ks] = STG_A + (uint32_t)(bRow0 * 128) + (((uint32_t)(bCol + ks * 32)) ^ bXor);
    }

    // producer
    const int pr = tid >> 3;
    const int pc = tid & 7;
    const uint32_t dstSw = SWZ128((uint32_t)(pr * 128 + pc * 16));
    const uint8_t* aSrc = (const uint8_t*)g_xb  + (size_t)(m0 + pr) * ROWB + kstart * 128 + pc * 16;
    const uint8_t* bSrc = (const uint8_t*)g_w1b + (size_t)(n0 + pr) * ROWB + kstart * 128 + pc * 16;

    float acc[2][8][4];
#pragma unroll
    for (int mi = 0; mi < 2; mi++)
#pragma unroll
        for (int ni = 0; ni < 8; ni++)
#pragma unroll
            for (int c = 0; c < 4; c++) acc[mi][ni][c] = 0.0f;

    auto load_stage = [&](uint32_t stgOff) {
        uint32_t d = sbase + stgOff + dstSw;
#pragma unroll
        for (int it = 0; it < 4; ++it) {
            asm volatile("cp.async.cg.shared.global [%0], [%1], 16;"
                         :: "r"(d + it * 4096), "l"(aSrc + (size_t)it * 32 * ROWB) : "memory");
            asm volatile("cp.async.cg.shared.global [%0], [%1], 16;"
                         :: "r"(d + STG_A + it * 4096), "l"(bSrc + (size_t)it * 32 * ROWB) : "memory");
        }
        asm volatile("cp.async.commit_group;" ::: "memory");
        aSrc += 128; bSrc += 128;
    };

    load_stage(0);
    load_stage(STG_BYTES);
    uint32_t cOff = 0, lOff = 2 * STG_BYTES;

    for (int s = 0; s < nst; ++s) {
        asm volatile("cp.async.wait_group 1;" ::: "memory");
        __syncthreads();

        if (s + 2 < nst) {
            load_stage(lOff);
            lOff = (lOff == 2 * STG_BYTES) ? 0u : lOff + STG_BYTES;
        } else {
            asm volatile("cp.async.commit_group;" ::: "memory");
        }

        const uint32_t stg = sbase + cOff;
        cOff = (cOff == 2 * STG_BYTES) ? 0u : cOff + STG_BYTES;

#pragma unroll
        for (int ks = 0; ks < 4; ++ks) {
            const uint32_t bb = stg + bOff[ks];
            uint32_t b[8][2];
#pragma unroll
            for (int pp = 0; pp < 4; pp++) {
                uint32_t r0, r1, r2, r3;
                ldsm_x4(r0, r1, r2, r3, bb + pp * 2048);
                b[2 * pp][0] = r0; b[2 * pp][1] = r1;
                b[2 * pp + 1][0] = r2; b[2 * pp + 1][1] = r3;
            }
            const uint32_t aa = stg + aOff[ks];
            uint32_t a[2][4];
            ldsm_x4(a[0][0], a[0][1], a[0][2], a[0][3], aa);
            ldsm_x4(a[1][0], a[1][1], a[1][2], a[1][3], aa + 2048);
#pragma unroll
            for (int mi = 0; mi < 2; mi++)
#pragma unroll
                for (int ni = 0; ni < 8; ni++)
                    mma_bf16(acc[mi][ni], a[mi], b[ni]);
        }
    }
    __syncthreads();   // all LDSM done before buffers are reused

    const int qrow = lid >> 2;
    const int qcol = lid & 3;

    if (TAIL) {
        // store raw K-half partials (each element written exactly once)
#pragma unroll
        for (int mi = 0; mi < 2; mi++)
#pragma unroll
            for (int ni = 0; ni < 8; ni++) {
                int row = wm * 32 + mi * 16 + qrow;
                int col = wn * 64 + ni * 8 + qcol * 2;
                *(float2*)&hbuf[row * 128 + col]       = make_float2(acc[mi][ni][0], acc[mi][ni][1]);
                *(float2*)&hbuf[(row + 8) * 128 + col] = make_float2(acc[mi][ni][2], acc[mi][ni][3]);
            }
    } else {
        // fused epilogue: logits[m] += sum_n relu(acc + b1) * w2
#pragma unroll
        for (int mi = 0; mi < 2; mi++) {
            float r0 = 0.f, r1 = 0.f;
#pragma unroll
            for (int ni = 0; ni < 8; ni++) {
                int n = n0 + wn * 64 + ni * 8 + qcol * 2;
                float b1a = g_b1[n],     w2a = g_w2[n];
                float b1b = g_b1[n + 1], w2b = g_w2[n + 1];
                r0 += fmaxf(acc[mi][ni][0] + b1a, 0.f) * w2a
                    + fmaxf(acc[mi][ni][1] + b1b, 0.f) * w2b;
                r1 += fmaxf(acc[mi][ni][2] + b1a, 0.f) * w2a
                    + fmaxf(acc[mi][ni][3] + b1b, 0.f) * w2b;
            }
            r0 += __shfl_xor_sync(0xffffffffu, r0, 1);
            r0 += __shfl_xor_sync(0xffffffffu, r0, 2);
            r1 += __shfl_xor_sync(0xffffffffu, r1, 1);
            r1 += __shfl_xor_sync(0xffffffffu, r1, 2);
            if (qcol == 0) {
                int row = m0 + wm * 32 + mi * 16 + qrow;
                atomicAdd(&g_logits[row],     r0);
                atomicAdd(&g_logits[row + 8], r1);
            }
        }
    }
}

// ---- bf16 GEMM: 296 static full tiles + dynamic K-half tail items ----
__global__ __launch_bounds__(256, 2) void gemm_bf16() {
    extern __shared__ __align__(1024) uint8_t smem[];
    __shared__ int s_w;
    const uint32_t sbase = smem_u32(smem);
    const int tid = threadIdx.x;
    const int wid = tid >> 5;
    const int lid = tid & 31;

    // static full tile
    {
        const int t = blockIdx.x;
        do_tile<false>(sbase, (t / NT) * 128, (t % NT) * 128, 0, nullptr, tid, wid, lid);
    }

    // dynamic tail: K-half items of tiles 296..415
    for (;;) {
        if (tid == 0) s_w = atomicAdd(&g_counter, 1);
        __syncthreads();
        const int w = s_w;
        __syncthreads();
        if (w >= TAIL_ITEMS) break;
        const int ti = w >> 1;
        const int kh = w & 1;
        const int t  = FULL_T + ti;
        do_tile<true>(sbase, (t / NT) * 128, (t % NT) * 128,
                      kh * (KSTG / 2), &g_h[kh][ti][0], tid, wid, lid);
    }
}

// ---- tail merge: h = h0 + h1; logits += relu(h + b1) . w2 ----
__global__ __launch_bounds__(256) void tailfin() {
    const int b   = blockIdx.x;            // 0..119
    const int tid = threadIdx.x;
    const int t   = FULL_T + b;
    const int m0  = (t / NT) * 128;
    const int n0  = (t % NT) * 128;
    const float* h0 = &g_h[0][b][0];
    const float* h1 = &g_h[1][b][0];

    const int row  = tid >> 1;
    const int half = tid & 1;
    float s = 0.0f;
#pragma unroll 4
    for (int c = 0; c < 64; ++c) {
        int col = half * 64 + c;
        int idx = row * 128 + col;
        float v = h0[idx] + h1[idx] + g_b1[n0 + col];
        s += fmaxf(v, 0.0f) * g_w2[n0 + col];
    }
    s += __shfl_xor_sync(0xffffffffu, s, 1);
    if (!half) atomicAdd(&g_logits[m0 + row], s);
}

// ---------------- finalize ----------------
__global__ void finalize(const float* __restrict__ b2, float* __restrict__ out) {
    int i = blockIdx.x * blockDim.x + threadIdx.x;
    if (i < BATCH) {
        float z = g_logits[i] + b2[0];
        out[i] = 1.0f / (1.0f + expf(-z));
    }
}

// ---------------- launch ----------------
extern "C" void kernel_launch(void* const* d_in, const int* in_sizes, int n_in,
                              void* d_out, int out_size) {
    const float* sim = (const float*)d_in[0];
    const float* W1  = (const float*)d_in[1];
    const float* b1  = (const float*)d_in[2];
    const float* W2  = (const float*)d_in[3];
    const float* b2  = (const float*)d_in[4];
    float* out = (float*)d_out;

    cudaFuncSetAttribute(gemm_bf16, cudaFuncAttributeMaxDynamicSharedMemorySize, SMEM_TOTAL);

    prep_small<<<(BATCH + 255) / 256, 256>>>(b1, W2);
    prep_w1b<<<dim3((KP / 4 + 255) / 256, NP), 256>>>(W1);
    triub<<<BATCH, 256>>>(sim);
    gemm_bf16<<<GRID, 256, SMEM_TOTAL>>>();
    tailfin<<<TAIL_T, 256>>>();
    finalize<<<(BATCH + 255) / 256, 256>>>(b2, out);
}